// round 4
// baseline (speedup 1.0000x reference)
#include <cuda_runtime.h>
#include <cuda_bf16.h>
#include <stdint.h>
#include <math.h>

#define N_ROUTES 7
#define PC_DIM   512
#define MC_DIM   128
#define KCLS     25
#define BSZ      4096
#define COLS     (KCLS * MC_DIM)        // 3200
#define VOTE_PER_B (N_ROUTES * COLS)    // 22400
#define PP_STRIDE (N_ROUTES * PC_DIM)   // 3584

__device__ float g_vote[(size_t)BSZ * VOTE_PER_B];                    // 367 MB
__device__ __nv_bfloat16 g_Phi[(size_t)BSZ * PP_STRIDE];
__device__ __nv_bfloat16 g_Plo[(size_t)BSZ * PP_STRIDE];
__device__ __nv_bfloat16 g_Whi[(size_t)N_ROUTES * COLS * PC_DIM];     // [n][col][d]
__device__ __nv_bfloat16 g_Wlo[(size_t)N_ROUTES * COLS * PC_DIM];

__device__ __forceinline__ uint32_t smem_to_u32(const void* p) {
    uint32_t a;
    asm("{ .reg .u64 t; cvta.to.shared.u64 t, %1; cvt.u32.u64 %0, t; }"
        : "=r"(a) : "l"(p));
    return a;
}

// ---------------------------------------------------------------------------
// Prep 1: split prim_pose into bf16 hi/lo
// ---------------------------------------------------------------------------
__global__ __launch_bounds__(512) void prep_p_kernel(const float* __restrict__ P) {
    size_t i = (size_t)blockIdx.x * 512 + threadIdx.x;   // float4 index
    float4 x = ((const float4*)P)[i];
    __nv_bfloat16 h0 = __float2bfloat16(x.x);
    __nv_bfloat16 h1 = __float2bfloat16(x.y);
    __nv_bfloat16 h2 = __float2bfloat16(x.z);
    __nv_bfloat16 h3 = __float2bfloat16(x.w);
    __nv_bfloat162* dh = (__nv_bfloat162*)g_Phi;
    __nv_bfloat162* dl = (__nv_bfloat162*)g_Plo;
    dh[2 * i]     = __nv_bfloat162(h0, h1);
    dh[2 * i + 1] = __nv_bfloat162(h2, h3);
    dl[2 * i] = __nv_bfloat162(__float2bfloat16(x.x - __bfloat162float(h0)),
                               __float2bfloat16(x.y - __bfloat162float(h1)));
    dl[2 * i + 1] = __nv_bfloat162(__float2bfloat16(x.z - __bfloat162float(h2)),
                                   __float2bfloat16(x.w - __bfloat162float(h3)));
}

// ---------------------------------------------------------------------------
// Prep 2: transpose+split W[n][d][col] -> Whi/Wlo [n][col][d]
// ---------------------------------------------------------------------------
__global__ __launch_bounds__(256) void prep_w_kernel(const float* __restrict__ W) {
    __shared__ float tile[32][33];
    const int n = blockIdx.z;
    const int c0 = blockIdx.x * 32;
    const int d0 = blockIdx.y * 32;
    const float* Wn = W + (size_t)n * PC_DIM * COLS;
#pragma unroll
    for (int j = 0; j < 4; j++) {
        int d = d0 + threadIdx.y + j * 8;
        tile[threadIdx.y + j * 8][threadIdx.x] = Wn[(size_t)d * COLS + c0 + threadIdx.x];
    }
    __syncthreads();
#pragma unroll
    for (int j = 0; j < 4; j++) {
        int col = c0 + threadIdx.y + j * 8;
        int d = d0 + threadIdx.x;
        float x = tile[threadIdx.x][threadIdx.y + j * 8];
        __nv_bfloat16 h = __float2bfloat16(x);
        size_t o = ((size_t)n * COLS + col) * PC_DIM + d;
        g_Whi[o] = h;
        g_Wlo[o] = __float2bfloat16(x - __bfloat162float(h));
    }
}

// ---------------------------------------------------------------------------
// Vote GEMM: mma.sync bf16 3-term split. CTA tile 256x128, 512 threads,
// 16 warps (4 wm x 4 wn), warp tile 64x32. KCH=16, 4-stage cp.async.
// ---------------------------------------------------------------------------
#define KCH 16
#define ROWB 48                           // 32 B data + 16 pad
#define T_AH 0
#define T_AL 12288                        // 256*48
#define T_BH 24576
#define T_BL 30720                        // + 128*48
#define STG_BYTES 36864
#define NSTG 4
#define GEMM_SMEM (NSTG * STG_BYTES)      // 147456
#define NC (PC_DIM / KCH)                 // 32

#define CP_ASYNC(sa, ga) \
    asm volatile("cp.async.cg.shared.global [%0], [%1], 16;" :: "r"(sa), "l"(ga))
#define CP_COMMIT() asm volatile("cp.async.commit_group;" ::: "memory")
#define CP_WAIT(N)  asm volatile("cp.async.wait_group %0;" :: "n"(N))

#define LDSM_X4(r0, r1, r2, r3, a) \
    asm volatile("ldmatrix.sync.aligned.m8n8.x4.shared.b16 {%0,%1,%2,%3}, [%4];" \
        : "=r"(r0), "=r"(r1), "=r"(r2), "=r"(r3) : "r"(a))

#define MMA_BF16(d, a, b0, b1) \
    asm volatile("mma.sync.aligned.m16n8k16.row.col.f32.bf16.bf16.f32 " \
        "{%0,%1,%2,%3}, {%4,%5,%6,%7}, {%8,%9}, {%0,%1,%2,%3};" \
        : "+f"((d)[0]), "+f"((d)[1]), "+f"((d)[2]), "+f"((d)[3]) \
        : "r"((a)[0]), "r"((a)[1]), "r"((a)[2]), "r"((a)[3]), "r"(b0), "r"(b1))

__global__ __launch_bounds__(512, 1) void vote_gemm_tc(void) {
    extern __shared__ char smem[];
    const uint32_t sb = smem_to_u32(smem);
    const int tid  = threadIdx.x;
    const int lane = tid & 31;
    const int warp = tid >> 5;
    const int wm   = warp & 3;            // M block of 64
    const int wn   = warp >> 2;           // N block of 32

    const int n  = blockIdx.z;
    const int bm = blockIdx.y * 256;
    const int bn = blockIdx.x * 128;

    const __nv_bfloat16* Ahi = g_Phi + (size_t)bm * PP_STRIDE + (size_t)n * PC_DIM;
    const __nv_bfloat16* Alo = g_Plo + (size_t)bm * PP_STRIDE + (size_t)n * PC_DIM;
    const __nv_bfloat16* Bhi = g_Whi + ((size_t)n * COLS + bn) * PC_DIM;
    const __nv_bfloat16* Blo = g_Wlo + ((size_t)n * COLS + bn) * PC_DIM;

    float acc[4][4][4];
#pragma unroll
    for (int i = 0; i < 4; i++)
#pragma unroll
        for (int j = 0; j < 4; j++)
#pragma unroll
            for (int q = 0; q < 4; q++) acc[i][j][q] = 0.f;

    const int lrow = lane & 15, lch = lane >> 4;
    const uint32_t a_off0 = (uint32_t)((wm * 64 + lrow) * ROWB + lch * 16);
    const uint32_t b_off0 = (uint32_t)((wn * 32 + lrow) * ROWB + lch * 16);

    auto issue_stage = [&](int c, int buf) {
        const int k0 = c * KCH;
        const uint32_t sbase = sb + buf * STG_BYTES;
#pragma unroll
        for (int p = 0; p < 3; p++) {
            int id = p * 512 + tid;       // 0..1535
            if (id < 1024) {              // A hi/lo: 2 x 256 rows x 2 chunks
                int t = id >> 9, rem = id & 511, row = rem >> 1, ch = rem & 1;
                uint32_t sa = sbase + (t ? T_AL : T_AH) + row * ROWB + ch * 16;
                const __nv_bfloat16* g =
                    (t ? Alo : Ahi) + (size_t)row * PP_STRIDE + k0 + ch * 8;
                CP_ASYNC(sa, g);
            } else {                      // B hi/lo: 2 x 128 rows x 2 chunks
                int id2 = id - 1024;
                int t = id2 >> 8, rem = id2 & 255, row = rem >> 1, ch = rem & 1;
                uint32_t sa = sbase + (t ? T_BL : T_BH) + row * ROWB + ch * 16;
                const __nv_bfloat16* g =
                    (t ? Blo : Bhi) + (size_t)row * PC_DIM + k0 + ch * 8;
                CP_ASYNC(sa, g);
            }
        }
        CP_COMMIT();
    };

    issue_stage(0, 0);
    issue_stage(1, 1);
    issue_stage(2, 2);

    for (int c = 0; c < NC; c++) {
        if (c + 3 < NC) {
            issue_stage(c + 3, (c + 3) & 3);
            CP_WAIT(3);
        } else if (c == NC - 3) {
            CP_WAIT(2);
        } else if (c == NC - 2) {
            CP_WAIT(1);
        } else {
            CP_WAIT(0);
        }
        __syncthreads();

        const uint32_t sbase = sb + (c & 3) * STG_BYTES;
        uint32_t ah[4][4], al[4][4];
#pragma unroll
        for (int mt = 0; mt < 4; mt++) {
            uint32_t ao = a_off0 + mt * 16 * ROWB;
            LDSM_X4(ah[mt][0], ah[mt][1], ah[mt][2], ah[mt][3], sbase + T_AH + ao);
            LDSM_X4(al[mt][0], al[mt][1], al[mt][2], al[mt][3], sbase + T_AL + ao);
        }
#pragma unroll
        for (int g = 0; g < 2; g++) {
            uint32_t bo = b_off0 + g * 16 * ROWB;
            uint32_t bh[4], bl[4];
            LDSM_X4(bh[0], bh[1], bh[2], bh[3], sbase + T_BH + bo);
            LDSM_X4(bl[0], bl[1], bl[2], bl[3], sbase + T_BL + bo);
#pragma unroll
            for (int mt = 0; mt < 4; mt++) {
                MMA_BF16(acc[mt][g * 2 + 0], ah[mt], bh[0], bh[2]);
                MMA_BF16(acc[mt][g * 2 + 1], ah[mt], bh[1], bh[3]);
                MMA_BF16(acc[mt][g * 2 + 0], ah[mt], bl[0], bl[2]);
                MMA_BF16(acc[mt][g * 2 + 1], ah[mt], bl[1], bl[3]);
                MMA_BF16(acc[mt][g * 2 + 0], al[mt], bh[0], bh[2]);
                MMA_BF16(acc[mt][g * 2 + 1], al[mt], bh[1], bh[3]);
            }
        }
        __syncthreads();
    }

    // epilogue
#pragma unroll
    for (int mt = 0; mt < 4; mt++) {
#pragma unroll
        for (int j = 0; j < 4; j++) {
            int g = j >> 1, nt = j & 1;
            int row = bm + wm * 64 + mt * 16 + (lane >> 2);
            int col = bn + wn * 32 + g * 16 + nt * 8 + (lane & 3) * 2;
            float* d0 = g_vote + (size_t)row * VOTE_PER_B + (size_t)n * COLS + col;
            float* d1 = d0 + (size_t)8 * VOTE_PER_B;
            *(float2*)d0 = make_float2(acc[mt][j][0], acc[mt][j][1]);
            *(float2*)d1 = make_float2(acc[mt][j][2], acc[mt][j][3]);
        }
    }
}

// ---------------------------------------------------------------------------
// Register-resident routing: 800 threads = 25 warps, one warp per capsule m.
// Each lane keeps 7 x float4 of vote in registers for all iterations.
// ---------------------------------------------------------------------------
__device__ __forceinline__ float warp_sum(float v) {
#pragma unroll
    for (int o = 16; o; o >>= 1) v += __shfl_xor_sync(0xffffffffu, v, o);
    return v;
}

__global__ __launch_bounds__(800) void routing_kernel(
    const float* __restrict__ prim_act,
    const float* __restrict__ ln_gamma, const float* __restrict__ ln_beta,
    const float* __restrict__ embedding, const float* __restrict__ bias,
    float* __restrict__ out_logits, float* __restrict__ out_act,
    float* __restrict__ out_coef) {
    __shared__ float s_act[N_ROUTES];
    __shared__ float s_agree[N_ROUTES * KCLS];
    __shared__ float s_coef[N_ROUTES * KCLS];

    const int b    = blockIdx.x;
    const int tid  = threadIdx.x;
    const int lane = tid & 31;
    const int m    = tid >> 5;           // warp id == capsule index, 0..24

    // vote[b][n][m][lane*4 .. +4) in registers
    float4 v[N_ROUTES];
    {
        const float* base = g_vote + (size_t)b * VOTE_PER_B + m * MC_DIM + lane * 4;
#pragma unroll
        for (int nn = 0; nn < N_ROUTES; nn++)
            v[nn] = *(const float4*)(base + nn * COLS);
    }
    const float4 g4 = ((const float4*)ln_gamma)[lane];
    const float4 b4 = ((const float4*)ln_beta)[lane];
    if (tid < N_ROUTES) s_act[tid] = prim_act[(size_t)b * N_ROUTES + tid];
    __syncthreads();

    float a_r[N_ROUTES];
#pragma unroll
    for (int nn = 0; nn < N_ROUTES; nn++) a_r[nn] = s_act[nn];

    // ---- iteration 0: uniform coefficients ----
    float4 p = make_float4(0.f, 0.f, 0.f, 0.f);
#pragma unroll
    for (int nn = 0; nn < N_ROUTES; nn++) {
        p.x += a_r[nn] * v[nn].x;
        p.y += a_r[nn] * v[nn].y;
        p.z += a_r[nn] * v[nn].z;
        p.w += a_r[nn] * v[nn].w;
    }
    p.x *= (1.f / 25.f); p.y *= (1.f / 25.f); p.z *= (1.f / 25.f); p.w *= (1.f / 25.f);

    // warp-local LayerNorm over 128 dims
    auto layernorm = [&](float4& x) {
        float mu = warp_sum(x.x + x.y + x.z + x.w) * (1.f / MC_DIM);
        float dx = x.x - mu, dy = x.y - mu, dz = x.z - mu, dw = x.w - mu;
        float ve = warp_sum(dx * dx + dy * dy + dz * dz + dw * dw) * (1.f / MC_DIM)
                   + 1e-5f;
        float r = rsqrtf(ve);
        r = r * (1.5f - 0.5f * ve * r * r);
        x.x = dx * r * g4.x + b4.x;
        x.y = dy * r * g4.y + b4.y;
        x.z = dz * r * g4.z + b4.z;
        x.w = dw * r * g4.w + b4.w;
    };
    layernorm(p);

    const float scale = 0.08838834764831845f;   // 1/sqrt(128)
#pragma unroll
    for (int it = 1; it <= 2; it++) {
        // agree[n][m] = dot(v[n], p) * scale   (warp-local reduction)
#pragma unroll
        for (int nn = 0; nn < N_ROUTES; nn++) {
            float d = v[nn].x * p.x + v[nn].y * p.y + v[nn].z * p.z + v[nn].w * p.w;
            d = warp_sum(d);
            if (lane == 0) s_agree[nn * KCLS + m] = d * scale;
        }
        __syncthreads();

        // softmax over m per route (7 threads)
        if (tid < N_ROUTES) {
            float mx = -1e30f;
#pragma unroll
            for (int mm = 0; mm < KCLS; mm++)
                mx = fmaxf(mx, s_agree[tid * KCLS + mm]);
            float sum = 0.f;
#pragma unroll
            for (int mm = 0; mm < KCLS; mm++) {
                float e = expf(s_agree[tid * KCLS + mm] - mx);
                s_coef[tid * KCLS + mm] = e;
                sum += e;
            }
            float inv = 1.f / sum;
#pragma unroll
            for (int mm = 0; mm < KCLS; mm++) s_coef[tid * KCLS + mm] *= inv;
        }
        __syncthreads();

        if (it == 2 && tid < N_ROUTES * KCLS)
            out_coef[(size_t)b * (N_ROUTES * KCLS) + tid] = s_coef[tid];

        // pose[m] = sum_n coef[n][m]*act[n]*v[n]  (broadcast smem reads)
        p = make_float4(0.f, 0.f, 0.f, 0.f);
#pragma unroll
        for (int nn = 0; nn < N_ROUTES; nn++) {
            float ca = s_coef[nn * KCLS + m] * a_r[nn];
            p.x += ca * v[nn].x;
            p.y += ca * v[nn].y;
            p.z += ca * v[nn].z;
            p.w += ca * v[nn].w;
        }
        layernorm(p);
        __syncthreads();
    }

    // logits
    {
        const float4 e = ((const float4*)(embedding + (size_t)m * MC_DIM))[lane];
        float d = p.x * e.x + p.y * e.y + p.z * e.z + p.w * e.w;
        d = warp_sum(d);
        if (lane == 0) out_logits[(size_t)b * KCLS + m] = d + bias[m];
    }
    if (tid < N_ROUTES) out_act[(size_t)b * N_ROUTES + tid] = a_r[tid];
}

// ---------------------------------------------------------------------------
extern "C" void kernel_launch(void* const* d_in, const int* in_sizes, int n_in,
                              void* d_out, int out_size) {
    const float* prim_pose = (const float*)d_in[0];
    const float* prim_act  = (const float*)d_in[1];
    const float* w         = (const float*)d_in[2];
    const float* ln_gamma  = (const float*)d_in[3];
    const float* ln_beta   = (const float*)d_in[4];
    const float* embedding = (const float*)d_in[5];
    const float* bias      = (const float*)d_in[6];

    float* out        = (float*)d_out;
    float* out_logits = out;
    float* out_act    = out + (size_t)BSZ * KCLS;
    float* out_coef   = out_act + (size_t)BSZ * N_ROUTES;

    prep_p_kernel<<<(BSZ * PP_STRIDE) / 4 / 512, 512>>>(prim_pose);
    prep_w_kernel<<<dim3(COLS / 32, PC_DIM / 32, N_ROUTES), dim3(32, 8)>>>(w);

    cudaFuncSetAttribute(vote_gemm_tc,
                         cudaFuncAttributeMaxDynamicSharedMemorySize, GEMM_SMEM);
    dim3 g(COLS / 128, BSZ / 256, N_ROUTES);   // (25, 16, 7)
    vote_gemm_tc<<<g, 512, GEMM_SMEM>>>();

    routing_kernel<<<BSZ, 800>>>(prim_act, ln_gamma, ln_beta,
                                 embedding, bias,
                                 out_logits, out_act, out_coef);
}

// round 5
// speedup vs baseline: 1.3914x; 1.3914x over previous
#include <cuda_runtime.h>
#include <cuda_bf16.h>
#include <stdint.h>
#include <math.h>

#define N_ROUTES 7
#define PC_DIM   512
#define MC_DIM   128
#define KCLS     25
#define BSZ      4096
#define COLS     (KCLS * MC_DIM)        // 3200
#define VOTE_PER_B (N_ROUTES * COLS)    // 22400
#define PP_STRIDE (N_ROUTES * PC_DIM)   // 3584

__device__ float g_vote[(size_t)BSZ * VOTE_PER_B];                    // 367 MB
__device__ __nv_bfloat16 g_Phi[(size_t)BSZ * PP_STRIDE];
__device__ __nv_bfloat16 g_Plo[(size_t)BSZ * PP_STRIDE];
__device__ __nv_bfloat16 g_Whi[(size_t)N_ROUTES * COLS * PC_DIM];     // [n][col][d]
__device__ __nv_bfloat16 g_Wlo[(size_t)N_ROUTES * COLS * PC_DIM];

__device__ __forceinline__ uint32_t smem_to_u32(const void* p) {
    uint32_t a;
    asm("{ .reg .u64 t; cvta.to.shared.u64 t, %1; cvt.u32.u64 %0, t; }"
        : "=r"(a) : "l"(p));
    return a;
}
__device__ __forceinline__ uint32_t usw64(uint32_t o) {     // SW64 swizzle
    return o ^ ((o >> 3) & 0x30);
}

// ---------------------------------------------------------------------------
// Prep 1: split prim_pose into bf16 hi/lo
// ---------------------------------------------------------------------------
__global__ __launch_bounds__(512) void prep_p_kernel(const float* __restrict__ P) {
    size_t i = (size_t)blockIdx.x * 512 + threadIdx.x;   // float4 index
    float4 x = ((const float4*)P)[i];
    __nv_bfloat16 h0 = __float2bfloat16(x.x);
    __nv_bfloat16 h1 = __float2bfloat16(x.y);
    __nv_bfloat16 h2 = __float2bfloat16(x.z);
    __nv_bfloat16 h3 = __float2bfloat16(x.w);
    __nv_bfloat162* dh = (__nv_bfloat162*)g_Phi;
    __nv_bfloat162* dl = (__nv_bfloat162*)g_Plo;
    dh[2 * i]     = __nv_bfloat162(h0, h1);
    dh[2 * i + 1] = __nv_bfloat162(h2, h3);
    dl[2 * i] = __nv_bfloat162(__float2bfloat16(x.x - __bfloat162float(h0)),
                               __float2bfloat16(x.y - __bfloat162float(h1)));
    dl[2 * i + 1] = __nv_bfloat162(__float2bfloat16(x.z - __bfloat162float(h2)),
                                   __float2bfloat16(x.w - __bfloat162float(h3)));
}

// ---------------------------------------------------------------------------
// Prep 2: transpose+split W[n][d][col] -> Whi/Wlo [n][col][d]
// ---------------------------------------------------------------------------
__global__ __launch_bounds__(256) void prep_w_kernel(const float* __restrict__ W) {
    __shared__ float tile[32][33];
    const int n = blockIdx.z;
    const int c0 = blockIdx.x * 32;
    const int d0 = blockIdx.y * 32;
    const float* Wn = W + (size_t)n * PC_DIM * COLS;
#pragma unroll
    for (int j = 0; j < 4; j++) {
        int d = d0 + threadIdx.y + j * 8;
        tile[threadIdx.y + j * 8][threadIdx.x] = Wn[(size_t)d * COLS + c0 + threadIdx.x];
    }
    __syncthreads();
#pragma unroll
    for (int j = 0; j < 4; j++) {
        int col = c0 + threadIdx.y + j * 8;
        int d = d0 + threadIdx.x;
        float x = tile[threadIdx.x][threadIdx.y + j * 8];
        __nv_bfloat16 h = __float2bfloat16(x);
        size_t o = ((size_t)n * COLS + col) * PC_DIM + d;
        g_Whi[o] = h;
        g_Wlo[o] = __float2bfloat16(x - __bfloat162float(h));
    }
}

// ---------------------------------------------------------------------------
// Vote GEMM: mma.sync bf16 3-term split. CTA 128x128, 256 threads (8 warps,
// 4 wm x 2 wn, warp tile 32x64). KCH=32, 64B rows + SW64 swizzle, 3-stage
// cp.async, term-major MMA order (same-acc distance 4).
// ---------------------------------------------------------------------------
#define KCH 32
#define T_AH 0
#define T_AL 8192
#define T_BH 16384
#define T_BL 24576
#define STG_BYTES 32768
#define NSTG 3
#define GEMM_SMEM (NSTG * STG_BYTES)      // 98304 -> 2 CTAs/SM
#define NC (PC_DIM / KCH)                 // 16

#define CP_ASYNC(sa, ga) \
    asm volatile("cp.async.cg.shared.global [%0], [%1], 16;" :: "r"(sa), "l"(ga))
#define CP_COMMIT() asm volatile("cp.async.commit_group;" ::: "memory")
#define CP_WAIT(N)  asm volatile("cp.async.wait_group %0;" :: "n"(N))

#define LDSM_X4(r0, r1, r2, r3, a) \
    asm volatile("ldmatrix.sync.aligned.m8n8.x4.shared.b16 {%0,%1,%2,%3}, [%4];" \
        : "=r"(r0), "=r"(r1), "=r"(r2), "=r"(r3) : "r"(a))

#define MMA_BF16(d, a, b0, b1) \
    asm volatile("mma.sync.aligned.m16n8k16.row.col.f32.bf16.bf16.f32 " \
        "{%0,%1,%2,%3}, {%4,%5,%6,%7}, {%8,%9}, {%0,%1,%2,%3};" \
        : "+f"((d)[0]), "+f"((d)[1]), "+f"((d)[2]), "+f"((d)[3]) \
        : "r"((a)[0]), "r"((a)[1]), "r"((a)[2]), "r"((a)[3]), "r"(b0), "r"(b1))

__global__ __launch_bounds__(256, 2) void vote_gemm_tc(void) {
    extern __shared__ char smem[];
    const uint32_t sb = smem_to_u32(smem);
    const int tid  = threadIdx.x;
    const int lane = tid & 31;
    const int warp = tid >> 5;
    const int wm   = warp & 3;          // M block of 32
    const int wn   = warp >> 2;         // N block of 64

    const int n  = blockIdx.z;
    const int bm = blockIdx.y * 128;
    const int bn = blockIdx.x * 128;

    const __nv_bfloat16* Ahi = g_Phi + (size_t)bm * PP_STRIDE + (size_t)n * PC_DIM;
    const __nv_bfloat16* Alo = g_Plo + (size_t)bm * PP_STRIDE + (size_t)n * PC_DIM;
    const __nv_bfloat16* Bhi = g_Whi + ((size_t)n * COLS + bn) * PC_DIM;
    const __nv_bfloat16* Blo = g_Wlo + ((size_t)n * COLS + bn) * PC_DIM;

    float acc[2][8][4];
#pragma unroll
    for (int i = 0; i < 2; i++)
#pragma unroll
        for (int j = 0; j < 8; j++)
#pragma unroll
            for (int q = 0; q < 4; q++) acc[i][j][q] = 0.f;

    const int lrow = lane & 15, lch = lane >> 4;

    // cp.async mapping: 2048 chunks/stage, 8 per thread
    auto issue_stage = [&](int c, int buf) {
        const int k0 = c * KCH;
        const uint32_t sbase = sb + buf * STG_BYTES;
#pragma unroll
        for (int p = 0; p < 8; p++) {
            int id  = p * 256 + tid;
            int t   = id >> 9;          // 0..3
            int rem = id & 511;
            int row = rem >> 2;
            int ch  = rem & 3;
            uint32_t sa = sbase + t * 8192 + usw64(row * 64 + ch * 16);
            const __nv_bfloat16* g;
            if (t == 0)      g = Ahi + (size_t)row * PP_STRIDE + k0 + ch * 8;
            else if (t == 1) g = Alo + (size_t)row * PP_STRIDE + k0 + ch * 8;
            else if (t == 2) g = Bhi + (size_t)row * PC_DIM + k0 + ch * 8;
            else             g = Blo + (size_t)row * PC_DIM + k0 + ch * 8;
            CP_ASYNC(sa, g);
        }
        CP_COMMIT();
    };

    issue_stage(0, 0);
    issue_stage(1, 1);
    issue_stage(2, 2);

    for (int c = 0; c < NC; c++) {
        if (c <= NC - 3)      CP_WAIT(2);
        else if (c == NC - 2) CP_WAIT(1);
        else                  CP_WAIT(0);
        __syncthreads();

        const uint32_t sbase = sb + (c % 3) * STG_BYTES;
#pragma unroll
        for (int ks = 0; ks < 2; ks++) {
            const uint32_t kb = ks * 32 + lch * 16;
            uint32_t ah[2][4], al[2][4];
#pragma unroll
            for (int mt = 0; mt < 2; mt++) {
                uint32_t ao = usw64((wm * 32 + mt * 16 + lrow) * 64 + kb);
                LDSM_X4(ah[mt][0], ah[mt][1], ah[mt][2], ah[mt][3], sbase + T_AH + ao);
                LDSM_X4(al[mt][0], al[mt][1], al[mt][2], al[mt][3], sbase + T_AL + ao);
            }
#pragma unroll
            for (int g = 0; g < 4; g++) {
                uint32_t bo = usw64((wn * 64 + g * 16 + lrow) * 64 + kb);
                uint32_t bh[4], bl[4];
                LDSM_X4(bh[0], bh[1], bh[2], bh[3], sbase + T_BH + bo);
                LDSM_X4(bl[0], bl[1], bl[2], bl[3], sbase + T_BL + bo);
                // term-major: same accumulator re-touched at distance 4
                MMA_BF16(acc[0][g * 2 + 0], ah[0], bh[0], bh[2]);
                MMA_BF16(acc[0][g * 2 + 1], ah[0], bh[1], bh[3]);
                MMA_BF16(acc[1][g * 2 + 0], ah[1], bh[0], bh[2]);
                MMA_BF16(acc[1][g * 2 + 1], ah[1], bh[1], bh[3]);
                MMA_BF16(acc[0][g * 2 + 0], ah[0], bl[0], bl[2]);
                MMA_BF16(acc[0][g * 2 + 1], ah[0], bl[1], bl[3]);
                MMA_BF16(acc[1][g * 2 + 0], ah[1], bl[0], bl[2]);
                MMA_BF16(acc[1][g * 2 + 1], ah[1], bl[1], bl[3]);
                MMA_BF16(acc[0][g * 2 + 0], al[0], bh[0], bh[2]);
                MMA_BF16(acc[0][g * 2 + 1], al[0], bh[1], bh[3]);
                MMA_BF16(acc[1][g * 2 + 0], al[1], bh[0], bh[2]);
                MMA_BF16(acc[1][g * 2 + 1], al[1], bh[1], bh[3]);
            }
        }
        __syncthreads();
        if (c + 3 < NC) issue_stage(c + 3, (c + 3) % 3);
    }

    // epilogue: direct fp32 stores
#pragma unroll
    for (int mt = 0; mt < 2; mt++) {
#pragma unroll
        for (int j = 0; j < 8; j++) {
            int g = j >> 1, nt = j & 1;
            int row = bm + wm * 32 + mt * 16 + (lane >> 2);
            int col = bn + wn * 64 + g * 16 + nt * 8 + (lane & 3) * 2;
            float* d0 = g_vote + (size_t)row * VOTE_PER_B + (size_t)n * COLS + col;
            float* d1 = d0 + (size_t)8 * VOTE_PER_B;
            *(float2*)d0 = make_float2(acc[mt][j][0], acc[mt][j][1]);
            *(float2*)d1 = make_float2(acc[mt][j][2], acc[mt][j][3]);
        }
    }
}

// ---------------------------------------------------------------------------
// Register-resident routing: 800 threads = 25 warps, one warp per capsule m.
// Warp-parallel softmax; fused mean/var LN reduction.
// ---------------------------------------------------------------------------
__device__ __forceinline__ float warp_sum(float v) {
#pragma unroll
    for (int o = 16; o; o >>= 1) v += __shfl_xor_sync(0xffffffffu, v, o);
    return v;
}
__device__ __forceinline__ float warp_max(float v) {
#pragma unroll
    for (int o = 16; o; o >>= 1) v = fmaxf(v, __shfl_xor_sync(0xffffffffu, v, o));
    return v;
}
// fused two-value reduction (mean & sumsq) — independent shfl pairs pipeline
__device__ __forceinline__ void warp_sum2(float& a, float& b) {
#pragma unroll
    for (int o = 16; o; o >>= 1) {
        a += __shfl_xor_sync(0xffffffffu, a, o);
        b += __shfl_xor_sync(0xffffffffu, b, o);
    }
}

__global__ __launch_bounds__(800) void routing_kernel(
    const float* __restrict__ prim_act,
    const float* __restrict__ ln_gamma, const float* __restrict__ ln_beta,
    const float* __restrict__ embedding, const float* __restrict__ bias,
    float* __restrict__ out_logits, float* __restrict__ out_act,
    float* __restrict__ out_coef) {
    __shared__ float s_act[N_ROUTES];
    __shared__ float s_agree[N_ROUTES * KCLS];
    __shared__ float s_coef[N_ROUTES * KCLS];

    const int b    = blockIdx.x;
    const int tid  = threadIdx.x;
    const int lane = tid & 31;
    const int m    = tid >> 5;           // warp id == capsule index, 0..24

    float4 v[N_ROUTES];
    {
        const float* base = g_vote + (size_t)b * VOTE_PER_B + m * MC_DIM + lane * 4;
#pragma unroll
        for (int nn = 0; nn < N_ROUTES; nn++)
            v[nn] = *(const float4*)(base + nn * COLS);
    }
    const float4 g4 = ((const float4*)ln_gamma)[lane];
    const float4 b4 = ((const float4*)ln_beta)[lane];
    if (tid < N_ROUTES) s_act[tid] = prim_act[(size_t)b * N_ROUTES + tid];
    __syncthreads();

    float a_r[N_ROUTES];
#pragma unroll
    for (int nn = 0; nn < N_ROUTES; nn++) a_r[nn] = s_act[nn];

    float4 p = make_float4(0.f, 0.f, 0.f, 0.f);
#pragma unroll
    for (int nn = 0; nn < N_ROUTES; nn++) {
        p.x += a_r[nn] * v[nn].x;
        p.y += a_r[nn] * v[nn].y;
        p.z += a_r[nn] * v[nn].z;
        p.w += a_r[nn] * v[nn].w;
    }
    p.x *= (1.f / 25.f); p.y *= (1.f / 25.f); p.z *= (1.f / 25.f); p.w *= (1.f / 25.f);

    auto layernorm = [&](float4& x) {
        float s1 = x.x + x.y + x.z + x.w;
        float s2 = x.x * x.x + x.y * x.y + x.z * x.z + x.w * x.w;
        warp_sum2(s1, s2);
        float mu = s1 * (1.f / MC_DIM);
        float ve = s2 * (1.f / MC_DIM) - mu * mu + 1e-5f;
        float r = rsqrtf(ve);
        r = r * (1.5f - 0.5f * ve * r * r);
        x.x = (x.x - mu) * r * g4.x + b4.x;
        x.y = (x.y - mu) * r * g4.y + b4.y;
        x.z = (x.z - mu) * r * g4.z + b4.z;
        x.w = (x.w - mu) * r * g4.w + b4.w;
    };
    layernorm(p);

    const float scale = 0.08838834764831845f;   // 1/sqrt(128)
#pragma unroll
    for (int it = 1; it <= 2; it++) {
        // agree[n][m] = dot(v[n], p) * scale
#pragma unroll
        for (int nn = 0; nn < N_ROUTES; nn++) {
            float d = v[nn].x * p.x + v[nn].y * p.y + v[nn].z * p.z + v[nn].w * p.w;
            d = warp_sum(d);
            if (lane == 0) s_agree[nn * KCLS + m] = d * scale;
        }
        __syncthreads();

        // warp-parallel softmax: warp nn, lane = class index
        if (m < N_ROUTES) {
            float aval = (lane < KCLS) ? s_agree[m * KCLS + lane] : -1e30f;
            float mx = warp_max(aval);
            float e = (lane < KCLS) ? expf(aval - mx) : 0.f;
            float s = warp_sum(e);
            if (lane < KCLS) s_coef[m * KCLS + lane] = e / s;
        }
        __syncthreads();

        if (it == 2 && tid < N_ROUTES * KCLS)
            out_coef[(size_t)b * (N_ROUTES * KCLS) + tid] = s_coef[tid];

        p = make_float4(0.f, 0.f, 0.f, 0.f);
#pragma unroll
        for (int nn = 0; nn < N_ROUTES; nn++) {
            float ca = s_coef[nn * KCLS + m] * a_r[nn];
            p.x += ca * v[nn].x;
            p.y += ca * v[nn].y;
            p.z += ca * v[nn].z;
            p.w += ca * v[nn].w;
        }
        layernorm(p);
        __syncthreads();
    }

    {
        const float4 e = ((const float4*)(embedding + (size_t)m * MC_DIM))[lane];
        float d = p.x * e.x + p.y * e.y + p.z * e.z + p.w * e.w;
        d = warp_sum(d);
        if (lane == 0) out_logits[(size_t)b * KCLS + m] = d + bias[m];
    }
    if (tid < N_ROUTES) out_act[(size_t)b * N_ROUTES + tid] = a_r[tid];
}

// ---------------------------------------------------------------------------
extern "C" void kernel_launch(void* const* d_in, const int* in_sizes, int n_in,
                              void* d_out, int out_size) {
    const float* prim_pose = (const float*)d_in[0];
    const float* prim_act  = (const float*)d_in[1];
    const float* w         = (const float*)d_in[2];
    const float* ln_gamma  = (const float*)d_in[3];
    const float* ln_beta   = (const float*)d_in[4];
    const float* embedding = (const float*)d_in[5];
    const float* bias      = (const float*)d_in[6];

    float* out        = (float*)d_out;
    float* out_logits = out;
    float* out_act    = out + (size_t)BSZ * KCLS;
    float* out_coef   = out_act + (size_t)BSZ * N_ROUTES;

    prep_p_kernel<<<(BSZ * PP_STRIDE) / 4 / 512, 512>>>(prim_pose);
    prep_w_kernel<<<dim3(COLS / 32, PC_DIM / 32, N_ROUTES), dim3(32, 8)>>>(w);

    cudaFuncSetAttribute(vote_gemm_tc,
                         cudaFuncAttributeMaxDynamicSharedMemorySize, GEMM_SMEM);
    dim3 g(COLS / 128, BSZ / 128, N_ROUTES);   // (25, 32, 7)
    vote_gemm_tc<<<g, 256, GEMM_SMEM>>>();

    routing_kernel<<<BSZ, 800>>>(prim_act, ln_gamma, ln_beta,
                                 embedding, bias,
                                 out_logits, out_act, out_coef);
}